// round 16
// baseline (speedup 1.0000x reference)
#include <cuda_runtime.h>
#include <cuda_bf16.h>

#define NCELLS 8192
#define NCOLS  1024
#define ROWS_PER_BLOCK 8
#define BLOCK_THREADS 256
#define GROUPS 8             // 8 groups x 8 unroll x 32 lanes = 2048 vec/row

// --------------------------------------------------------------------------
// Single fused kernel — measured-best structure (R5/R10/R13/R14/R15):
// batched-phase loads, predicated-FADD counting, anomaly barrier restricted
// to block 0. Sits at the mixed-R/W HBM roofline (~5.69 TB/s, 70-72% of
// spec, stable across 5 identical-binary runs) with provably minimal
// traffic (W read once, written once).
//  Phase A (all blocks, redundant): build a 8192-bit new_active bitmask in
//  shared memory from predictive/active_columns (L2-resident reads).
//  Block 0 additionally writes new_active[8192] and anomaly[1].
//  Phase B: warp-per-row stream over segment_weights (read+write 512MB):
//    batched 8x LDG.128 + 8x LDS per group (all L1 work in the load phase),
//    presyn count -> new_predictive, permanence update -> Wout.
//  Output W region is misaligned by 1 float (flat offset 16385), so vector
//  stores use a shifted window [4i-1, 4i+2] assembled via shfl carry
//  (each resulting STG.128 is 16B-aligned; warp spans start 128B-aligned).
// --------------------------------------------------------------------------
__global__ void __launch_bounds__(BLOCK_THREADS, 4)
htm_fused(const float* __restrict__ active_columns,
          const float* __restrict__ W,
          const float* __restrict__ predictive,
          const float* __restrict__ prev,
          float* __restrict__ o_na,
          float* __restrict__ o_pred,
          float* __restrict__ o_anom,
          float* __restrict__ o_W) {
    __shared__ unsigned s_bits[256];   // bit j of word t = new_active[32t+j]
    __shared__ int s_cnt[2];

    const int tid = threadIdx.x;
    if (tid < 2) s_cnt[tid] = 0;

    // ---- Phase A: bitmask for columns 4*tid .. 4*tid+3 ----
    unsigned word = 0;
    int na_c = 0, np_c = 0;
#pragma unroll
    for (int cc = 0; cc < 4; ++cc) {
        int c = tid * 4 + cc;
        const float4* p4 = (const float4*)(predictive + c * 8);
        float4 a = __ldg(p4 + 0);
        float4 b = __ldg(p4 + 1);
        bool act = __ldg(active_columns + c) > 0.f;
        unsigned pb = (a.x > 0.f ? 1u : 0u) | (a.y > 0.f ? 2u : 0u) |
                      (a.z > 0.f ? 4u : 0u) | (a.w > 0.f ? 8u : 0u) |
                      (b.x > 0.f ? 16u : 0u) | (b.y > 0.f ? 32u : 0u) |
                      (b.z > 0.f ? 64u : 0u) | (b.w > 0.f ? 128u : 0u);
        bool has = pb != 0u;
        unsigned byte = act ? (has ? pb : 0xFFu) : 0u;
        word |= byte << (8 * cc);
        na_c += act ? 1 : 0;
        np_c += (act && has) ? 1 : 0;
    }
    s_bits[tid] = word;
    __syncthreads();   // s_cnt init + s_bits visible

    if (blockIdx.x == 0) {
        // new_active: cells 32*tid .. 32*tid+31
        float4* na4 = (float4*)(o_na + tid * 32);
#pragma unroll
        for (int q = 0; q < 8; ++q) {
            unsigned nb = (word >> (q * 4)) & 0xFu;
            na4[q] = make_float4((nb & 1) ? 1.f : 0.f, (nb & 2) ? 1.f : 0.f,
                                 (nb & 4) ? 1.f : 0.f, (nb & 8) ? 1.f : 0.f);
        }
        if (na_c | np_c) {
            if (na_c) atomicAdd(&s_cnt[0], na_c);
            if (np_c) atomicAdd(&s_cnt[1], np_c);
        }
        __syncthreads();   // only block 0 needs s_cnt complete
        if (tid == 0) {
            int na = s_cnt[0], np = s_cnt[1];
            int den = na > 1 ? na : 1;
            o_anom[0] = 1.0f - (float)np / (float)den;
        }
    }

    // ---- Phase B: stream one row per warp ----
    const int warp = tid >> 5;
    const int lane = tid & 31;
    const int row = blockIdx.x * ROWS_PER_BLOCK + warp;
    const int shft = 4 * (lane & 7);          // nibble position, constant/lane
    const int widx = lane >> 3;               // word sub-index, constant/lane

    const float4* wrow = (const float4*)(W + (size_t)row * NCELLS);
    float* orow = o_W + (size_t)row * NCELLS;
    const float prev_i = __ldg(prev + row);

    float cnt = 0.f;
    float carry = 0.f;

#pragma unroll 1
    for (int g = 0; g < GROUPS; ++g) {
        float4 w[8];
        unsigned m[8];
        // batched loads: 8 LDG.128 in flight per warp; LDS kept in this phase
#pragma unroll
        for (int k = 0; k < 8; ++k) {
            int t = g * 8 + k;
            w[k] = __ldcs(wrow + t * 32 + lane);
            m[k] = s_bits[t * 4 + widx];
        }
#pragma unroll
        for (int k = 0; k < 8; ++k) {
            int t = g * 8 + k;
            int i = t * 32 + lane;
            unsigned nib = (m[k] >> shft) & 0xFu;
            float4 ww = w[k];

            if ((nib & 1u) && ww.x >= 0.5f) cnt += 1.f;
            if ((nib & 2u) && ww.y >= 0.5f) cnt += 1.f;
            if ((nib & 4u) && ww.z >= 0.5f) cnt += 1.f;
            if ((nib & 8u) && ww.w >= 0.5f) cnt += 1.f;

            // coeff: +0.1 if active, -0.01 if not (exact vs reference)
            float cx = (nib & 1u) ? 0.1f : -0.01f;
            float cy = (nib & 2u) ? 0.1f : -0.01f;
            float cz = (nib & 4u) ? 0.1f : -0.01f;
            float cw = (nib & 8u) ? 0.1f : -0.01f;
            float ox = fminf(fmaxf(fmaf(prev_i, cx, ww.x), 0.f), 1.f);
            float oy = fminf(fmaxf(fmaf(prev_i, cy, ww.y), 0.f), 1.f);
            float oz = fminf(fmaxf(fmaf(prev_i, cz, ww.z), 0.f), 1.f);
            float ow = fminf(fmaxf(fmaf(prev_i, cw, ww.w), 0.f), 1.f);

            // shifted 16B-aligned store window [4i-1 .. 4i+2]
            float upw = __shfl_up_sync(0xFFFFFFFFu, ow, 1);
            float pw = (lane == 0) ? carry : upw;
            carry = __shfl_sync(0xFFFFFFFFu, ow, 31);

            if (t == 0 && lane == 0) {
                __stcs(orow + 0, ox);
                __stcs(orow + 1, oy);
                __stcs(orow + 2, oz);
            } else {
                __stcs((float4*)(orow + 4 * i - 1), make_float4(pw, ox, oy, oz));
            }
        }
    }

    // row tail: element 8191 (uniform in carry)
    if (lane == 0)
        __stcs(orow + NCELLS - 1, carry);

    // presyn reduction (exact integer counts in f32)
#pragma unroll
    for (int o = 16; o; o >>= 1)
        cnt += __shfl_xor_sync(0xFFFFFFFFu, cnt, o);

    if (lane == 0)
        o_pred[row] = (cnt >= 13.0f) ? 1.0f : 0.0f;
}

// --------------------------------------------------------------------------
// Output layout (tuple order, flat):
//   [0 : 8192)                 new_active
//   [8192 : 16384)             new_predictive
//   [16384]                    anomaly
//   [16385 : 16385 + 8192^2)   new_segment_weights
// --------------------------------------------------------------------------
extern "C" void kernel_launch(void* const* d_in, const int* in_sizes, int n_in,
                              void* d_out, int out_size) {
    const float* active_columns = (const float*)d_in[0];
    const float* W              = (const float*)d_in[1];
    const float* predictive     = (const float*)d_in[2];
    const float* prev           = (const float*)d_in[3];

    float* out    = (float*)d_out;
    float* o_na   = out;
    float* o_pred = out + NCELLS;
    float* o_anom = out + 2 * NCELLS;
    float* o_W    = out + 2 * NCELLS + 1;

    htm_fused<<<NCELLS / ROWS_PER_BLOCK, BLOCK_THREADS>>>(
        active_columns, W, predictive, prev, o_na, o_pred, o_anom, o_W);
}

// round 17
// speedup vs baseline: 1.0003x; 1.0003x over previous
#include <cuda_runtime.h>
#include <cuda_bf16.h>

#define NCELLS 8192
#define NCOLS  1024
#define ROWS_PER_BLOCK 8
#define BLOCK_THREADS 256
#define GROUPS 8             // 8 groups x 8 unroll x 32 lanes = 2048 vec/row

// --------------------------------------------------------------------------
// Single fused kernel — measured-best structure (stable across 6
// identical-binary runs: kernel 86.0±0.6us, DRAM 70-72%): batched-phase
// loads, predicated-FADD counting, anomaly barrier restricted to block 0.
// Sits at the mixed-R/W HBM roofline (~5.66 TB/s) with provably minimal
// traffic (W read once, written once).
//  Phase A (all blocks, redundant): build a 8192-bit new_active bitmask in
//  shared memory from predictive/active_columns (L2-resident reads).
//  Block 0 additionally writes new_active[8192] and anomaly[1].
//  Phase B: warp-per-row stream over segment_weights (read+write 512MB):
//    batched 8x LDG.128 + 8x LDS per group (all L1 work in the load phase),
//    presyn count -> new_predictive, permanence update -> Wout.
//  Output W region is misaligned by 1 float (flat offset 16385), so vector
//  stores use a shifted window [4i-1, 4i+2] assembled via shfl carry
//  (each resulting STG.128 is 16B-aligned; warp spans start 128B-aligned).
// --------------------------------------------------------------------------
__global__ void __launch_bounds__(BLOCK_THREADS, 4)
htm_fused(const float* __restrict__ active_columns,
          const float* __restrict__ W,
          const float* __restrict__ predictive,
          const float* __restrict__ prev,
          float* __restrict__ o_na,
          float* __restrict__ o_pred,
          float* __restrict__ o_anom,
          float* __restrict__ o_W) {
    __shared__ unsigned s_bits[256];   // bit j of word t = new_active[32t+j]
    __shared__ int s_cnt[2];

    const int tid = threadIdx.x;
    if (tid < 2) s_cnt[tid] = 0;

    // ---- Phase A: bitmask for columns 4*tid .. 4*tid+3 ----
    unsigned word = 0;
    int na_c = 0, np_c = 0;
#pragma unroll
    for (int cc = 0; cc < 4; ++cc) {
        int c = tid * 4 + cc;
        const float4* p4 = (const float4*)(predictive + c * 8);
        float4 a = __ldg(p4 + 0);
        float4 b = __ldg(p4 + 1);
        bool act = __ldg(active_columns + c) > 0.f;
        unsigned pb = (a.x > 0.f ? 1u : 0u) | (a.y > 0.f ? 2u : 0u) |
                      (a.z > 0.f ? 4u : 0u) | (a.w > 0.f ? 8u : 0u) |
                      (b.x > 0.f ? 16u : 0u) | (b.y > 0.f ? 32u : 0u) |
                      (b.z > 0.f ? 64u : 0u) | (b.w > 0.f ? 128u : 0u);
        bool has = pb != 0u;
        unsigned byte = act ? (has ? pb : 0xFFu) : 0u;
        word |= byte << (8 * cc);
        na_c += act ? 1 : 0;
        np_c += (act && has) ? 1 : 0;
    }
    s_bits[tid] = word;
    __syncthreads();   // s_cnt init + s_bits visible

    if (blockIdx.x == 0) {
        // new_active: cells 32*tid .. 32*tid+31
        float4* na4 = (float4*)(o_na + tid * 32);
#pragma unroll
        for (int q = 0; q < 8; ++q) {
            unsigned nb = (word >> (q * 4)) & 0xFu;
            na4[q] = make_float4((nb & 1) ? 1.f : 0.f, (nb & 2) ? 1.f : 0.f,
                                 (nb & 4) ? 1.f : 0.f, (nb & 8) ? 1.f : 0.f);
        }
        if (na_c | np_c) {
            if (na_c) atomicAdd(&s_cnt[0], na_c);
            if (np_c) atomicAdd(&s_cnt[1], np_c);
        }
        __syncthreads();   // only block 0 needs s_cnt complete
        if (tid == 0) {
            int na = s_cnt[0], np = s_cnt[1];
            int den = na > 1 ? na : 1;
            o_anom[0] = 1.0f - (float)np / (float)den;
        }
    }

    // ---- Phase B: stream one row per warp ----
    const int warp = tid >> 5;
    const int lane = tid & 31;
    const int row = blockIdx.x * ROWS_PER_BLOCK + warp;
    const int shft = 4 * (lane & 7);          // nibble position, constant/lane
    const int widx = lane >> 3;               // word sub-index, constant/lane

    const float4* wrow = (const float4*)(W + (size_t)row * NCELLS);
    float* orow = o_W + (size_t)row * NCELLS;
    const float prev_i = __ldg(prev + row);

    float cnt = 0.f;
    float carry = 0.f;

#pragma unroll 1
    for (int g = 0; g < GROUPS; ++g) {
        float4 w[8];
        unsigned m[8];
        // batched loads: 8 LDG.128 in flight per warp; LDS kept in this phase
#pragma unroll
        for (int k = 0; k < 8; ++k) {
            int t = g * 8 + k;
            w[k] = __ldcs(wrow + t * 32 + lane);
            m[k] = s_bits[t * 4 + widx];
        }
#pragma unroll
        for (int k = 0; k < 8; ++k) {
            int t = g * 8 + k;
            int i = t * 32 + lane;
            unsigned nib = (m[k] >> shft) & 0xFu;
            float4 ww = w[k];

            if ((nib & 1u) && ww.x >= 0.5f) cnt += 1.f;
            if ((nib & 2u) && ww.y >= 0.5f) cnt += 1.f;
            if ((nib & 4u) && ww.z >= 0.5f) cnt += 1.f;
            if ((nib & 8u) && ww.w >= 0.5f) cnt += 1.f;

            // coeff: +0.1 if active, -0.01 if not (exact vs reference)
            float cx = (nib & 1u) ? 0.1f : -0.01f;
            float cy = (nib & 2u) ? 0.1f : -0.01f;
            float cz = (nib & 4u) ? 0.1f : -0.01f;
            float cw = (nib & 8u) ? 0.1f : -0.01f;
            float ox = fminf(fmaxf(fmaf(prev_i, cx, ww.x), 0.f), 1.f);
            float oy = fminf(fmaxf(fmaf(prev_i, cy, ww.y), 0.f), 1.f);
            float oz = fminf(fmaxf(fmaf(prev_i, cz, ww.z), 0.f), 1.f);
            float ow = fminf(fmaxf(fmaf(prev_i, cw, ww.w), 0.f), 1.f);

            // shifted 16B-aligned store window [4i-1 .. 4i+2]
            float upw = __shfl_up_sync(0xFFFFFFFFu, ow, 1);
            float pw = (lane == 0) ? carry : upw;
            carry = __shfl_sync(0xFFFFFFFFu, ow, 31);

            if (t == 0 && lane == 0) {
                __stcs(orow + 0, ox);
                __stcs(orow + 1, oy);
                __stcs(orow + 2, oz);
            } else {
                __stcs((float4*)(orow + 4 * i - 1), make_float4(pw, ox, oy, oz));
            }
        }
    }

    // row tail: element 8191 (uniform in carry)
    if (lane == 0)
        __stcs(orow + NCELLS - 1, carry);

    // presyn reduction (exact integer counts in f32)
#pragma unroll
    for (int o = 16; o; o >>= 1)
        cnt += __shfl_xor_sync(0xFFFFFFFFu, cnt, o);

    if (lane == 0)
        o_pred[row] = (cnt >= 13.0f) ? 1.0f : 0.0f;
}

// --------------------------------------------------------------------------
// Output layout (tuple order, flat):
//   [0 : 8192)                 new_active
//   [8192 : 16384)             new_predictive
//   [16384]                    anomaly
//   [16385 : 16385 + 8192^2)   new_segment_weights
// --------------------------------------------------------------------------
extern "C" void kernel_launch(void* const* d_in, const int* in_sizes, int n_in,
                              void* d_out, int out_size) {
    const float* active_columns = (const float*)d_in[0];
    const float* W              = (const float*)d_in[1];
    const float* predictive     = (const float*)d_in[2];
    const float* prev           = (const float*)d_in[3];

    float* out    = (float*)d_out;
    float* o_na   = out;
    float* o_pred = out + NCELLS;
    float* o_anom = out + 2 * NCELLS;
    float* o_W    = out + 2 * NCELLS + 1;

    htm_fused<<<NCELLS / ROWS_PER_BLOCK, BLOCK_THREADS>>>(
        active_columns, W, predictive, prev, o_na, o_pred, o_anom, o_W);
}